// round 2
// baseline (speedup 1.0000x reference)
#include <cuda_runtime.h>

#define BB 16
#define CC 64
#define NN 2048
#define TQ 128
#define TM 128
#define SROW 129   // padded row stride for S: conflict-free scans

// Scratch (no allocations allowed)
__device__ int g_idx[BB * NN * 8];

typedef unsigned long long ull;

__device__ __forceinline__ ull pack2(float lo, float hi) {
    ull r;
    asm("mov.b64 %0, {%1, %2};" : "=l"(r) : "f"(lo), "f"(hi));
    return r;
}
__device__ __forceinline__ ull fma2(ull a, ull b, ull c) {
    ull d;
    asm("fma.rn.f32x2 %0, %1, %2, %3;" : "=l"(d) : "l"(a), "l"(b), "l"(c));
    return d;
}
__device__ __forceinline__ float2 unpack2(ull a) {
    float2 f;
    asm("mov.b64 {%0, %1}, %2;" : "=f"(f.x), "=f"(f.y) : "l"(a));
    return f;
}

// ---------------------------------------------------------------------------
// KNN top-8 (top-9 incl. self, drop rank 0).
// CTA: 128 queries x full m sweep. 256 threads, 8x8 register tiles, f32x2 FMA.
// Shared: Qs[64][128] | S[128][129] (first 32KB aliased as Ms[64][128]) | xxs[128]
// Candidate norms computed inline from the resident Ms tile.
// Scan: thread t handles m-half 0, thread t+128 handles m-half 1 of query t&127;
// persistent per-thread top-9, single stable merge at the end.
// ---------------------------------------------------------------------------
__global__ void __launch_bounds__(256, 2) knn_kernel(const float* __restrict__ x) {
    extern __shared__ float sm[];
    float* Qs  = sm;                    // CC*TQ floats
    float* S   = sm + CC * TQ;          // TQ*SROW floats
    float* Ms  = S;                     // aliases first CC*TM floats of S
    float* xxs = S + TQ * SROW;         // TM floats

    const int b     = blockIdx.y;
    const int qbase = blockIdx.x * TQ;
    const int tid   = threadIdx.x;
    const int ty    = (tid & 255) >> 4; // 0..15
    const int tx    = tid & 15;         // 0..15
    const float* xb = x + b * CC * NN;

    // Load query tile Qs[c][q]
    for (int i = tid; i < (CC * TQ) / 4; i += 256) {
        int c = (i * 4) / TQ;
        int q = (i * 4) % TQ;
        *(float4*)&Qs[c * TQ + q] = *(const float4*)&xb[c * NN + qbase + q];
    }

    float val9[9];
    int   idx9[9];
#pragma unroll
    for (int k = 0; k < 9; ++k) { val9[k] = -3.4e38f; idx9[k] = -1; }

    const int qown = tid & 127;         // query this thread scans
    const int half = tid >> 7;          // which 64-wide m-half

    for (int mb = 0; mb < NN; mb += TM) {
        __syncthreads();   // previous scan done before Ms overwrites S / Qs ready

        // Load candidate tile Ms[c][m]
        for (int i = tid; i < (CC * TM) / 4; i += 256) {
            int c = (i * 4) / TM;
            int m = (i * 4) % TM;
            *(float4*)&Ms[c * TM + m] = *(const float4*)&xb[c * NN + mb + m];
        }
        __syncthreads();

        // Inline candidate norms: xxs[m] = sum_c Ms[c][m]^2 (threads 0..127)
        if (tid < TM) {
            float s0 = 0.f, s1 = 0.f;
#pragma unroll
            for (int c = 0; c < CC; c += 2) {
                float v0 = Ms[c * TM + tid];
                float v1 = Ms[(c + 1) * TM + tid];
                s0 = fmaf(v0, v0, s0);
                s1 = fmaf(v1, v1, s1);
            }
            xxs[tid] = s0 + s1;
        }

        // 128x128 dot-product tile, 8x8 per thread, packed f32x2 FMA
        ull acc[8][4];
#pragma unroll
        for (int i = 0; i < 8; ++i)
#pragma unroll
            for (int j = 0; j < 4; ++j) acc[i][j] = 0ull;

#pragma unroll 1
        for (int c = 0; c < CC; ++c) {
            float4 m0 = *(const float4*)&Ms[c * TM + tx * 8];
            float4 m1 = *(const float4*)&Ms[c * TM + tx * 8 + 4];
            float4 q0 = *(const float4*)&Qs[c * TQ + ty * 8];
            float4 q1 = *(const float4*)&Qs[c * TQ + ty * 8 + 4];
            ull mm[4];
            mm[0] = pack2(m0.x, m0.y);
            mm[1] = pack2(m0.z, m0.w);
            mm[2] = pack2(m1.x, m1.y);
            mm[3] = pack2(m1.z, m1.w);
            float qv[8] = {q0.x, q0.y, q0.z, q0.w, q1.x, q1.y, q1.z, q1.w};
#pragma unroll
            for (int i = 0; i < 8; ++i) {
                ull qq = pack2(qv[i], qv[i]);
#pragma unroll
                for (int j = 0; j < 4; ++j) acc[i][j] = fma2(qq, mm[j], acc[i][j]);
            }
        }
        __syncthreads();   // compute done; safe to overwrite Ms region with S

        // Spill tile to shared (padded stride)
#pragma unroll
        for (int i = 0; i < 8; ++i) {
            int q = ty * 8 + i;
#pragma unroll
            for (int j = 0; j < 4; ++j) {
                float2 f = unpack2(acc[i][j]);
                S[q * SROW + tx * 8 + j * 2]     = f.x;
                S[q * SROW + tx * 8 + j * 2 + 1] = f.y;
            }
        }
        __syncthreads();

        // Top-9 update: all 256 threads; each scans 64 candidates
        {
            const float* srow = &S[qown * SROW + half * 64];
            const float* xxh  = &xxs[half * 64];
            const int mofs = mb + half * 64;
            for (int m = 0; m < 64; ++m) {
                float v = fmaf(2.f, srow[m], -xxh[m]);
                if (v > val9[8]) {
                    val9[8] = v;
                    idx9[8] = mofs + m;
#pragma unroll
                    for (int k = 8; k > 0; --k) {
                        if (val9[k] > val9[k - 1]) {
                            float tv = val9[k]; val9[k] = val9[k - 1]; val9[k - 1] = tv;
                            int   ti = idx9[k]; idx9[k] = idx9[k - 1]; idx9[k - 1] = ti;
                        }
                    }
                }
            }
        }
    }

    // Final merge of the two half-lists per query (stable: val desc, idx asc)
    __syncthreads();
    float* MV = S;                       // [256][9] values
    int*   MI = (int*)(S + 256 * 9);     // [256][9] indices
#pragma unroll
    for (int k = 0; k < 9; ++k) {
        MV[tid * 9 + k] = val9[k];
        MI[tid * 9 + k] = idx9[k];
    }
    __syncthreads();
    if (tid < TQ) {
        const float* AV = &MV[tid * 9];
        const int*   AI = &MI[tid * 9];
        const float* BV = &MV[(tid + 128) * 9];
        const int*   BI = &MI[(tid + 128) * 9];
        int ia = 0, ib = 0;
        int q = qbase + tid;
        int* gout = &g_idx[(b * NN + q) * 8];
#pragma unroll
        for (int k = 0; k < 9; ++k) {
            float va = AV[ia], vb = BV[ib];
            bool takeA = (va > vb) || (va == vb && AI[ia] < BI[ib]);
            int  sel   = takeA ? AI[ia] : BI[ib];
            if (takeA) ++ia; else ++ib;
            if (k > 0) gout[k - 1] = sel;   // rank 0 is self
        }
    }
}

// ---------------------------------------------------------------------------
// Output assembly:
// out[b,c,n]   = x[b,c,n]
// out[b,c,N+n] = mean_k x[b,c,idx[b,n,k]]
// ---------------------------------------------------------------------------
__global__ void gather_kernel(const float* __restrict__ x, float* __restrict__ out) {
    __shared__ float row[NN];
    int b = blockIdx.x >> 6;
    int c = blockIdx.x & 63;
    const float* xr = x + (b * CC + c) * NN;
    for (int n = threadIdx.x; n < NN; n += blockDim.x) row[n] = xr[n];
    __syncthreads();
    const int* gi = g_idx + b * NN * 8;
    float* o = out + (size_t)(b * CC + c) * (2 * NN);
    for (int n = threadIdx.x; n < NN; n += blockDim.x) {
        o[n] = row[n];
        const int* gn = gi + n * 8;
        float s = 0.f;
#pragma unroll
        for (int k = 0; k < 8; ++k) s += row[gn[k]];
        o[NN + n] = s * 0.125f;
    }
}

// ---------------------------------------------------------------------------
extern "C" void kernel_launch(void* const* d_in, const int* in_sizes, int n_in,
                              void* d_out, int out_size) {
    (void)in_sizes; (void)n_in; (void)out_size;
    const float* x = (const float*)d_in[0];
    float* out = (float*)d_out;

    size_t smem = (size_t)(CC * TQ + TQ * SROW + TM) * sizeof(float);  // 99328 B
    cudaFuncSetAttribute(knn_kernel, cudaFuncAttributeMaxDynamicSharedMemorySize,
                         (int)smem);
    knn_kernel<<<dim3(NN / TQ, BB), 256, smem>>>(x);

    gather_kernel<<<BB * CC, 256>>>(x, out);
}

// round 4
// speedup vs baseline: 1.3933x; 1.3933x over previous
#include <cuda_runtime.h>
#include <cuda_bf16.h>
#include <cstdint>

#define BB 16
#define CC 64
#define NN 2048
#define TQ 64      // queries per CTA
#define TM 128     // candidates per tile
#define RS 144     // bf16 tile row stride in BYTES (128 data + 16 pad: conflict-free ldmatrix)
#define SROW 129   // fp32 score-tile row stride (odd: conflict-free column scans)

// ---------------- scratch (no allocation allowed) ----------------
__device__ __nv_bfloat16 g_hi[BB * NN * CC];   // [b][n][c], 128B rows
__device__ __nv_bfloat16 g_lo[BB * NN * CC];
__device__ float         g_xx[BB * NN];
__device__ int           g_idx[BB * NN * 8];

// smem byte offsets
#define QHI 0
#define QLO (QHI + TQ * RS)            // 9216
#define MHI (QLO + TQ * RS)            // 18432
#define MLO (MHI + TM * RS)            // 36864
#define SOF (MLO + TM * RS)            // 55296: S[64][129] fp32 = 33024B
#define XXS (SOF + TQ * SROW * 4)      // 88320
#define SM_TOTAL (XXS + TM * 4)        // 88832

__device__ __forceinline__ uint32_t smem_u32(const void* p) {
    uint32_t a;
    asm("{ .reg .u64 t; cvta.to.shared.u64 t, %1; cvt.u32.u64 %0, t; }" : "=r"(a) : "l"(p));
    return a;
}
__device__ __forceinline__ void ldsm4(uint32_t& r0, uint32_t& r1, uint32_t& r2, uint32_t& r3,
                                      uint32_t addr) {
    asm volatile("ldmatrix.sync.aligned.m8n8.x4.shared.b16 {%0,%1,%2,%3}, [%4];"
                 : "=r"(r0), "=r"(r1), "=r"(r2), "=r"(r3) : "r"(addr));
}
__device__ __forceinline__ void mma16816(float* c, const uint32_t* a, uint32_t b0, uint32_t b1) {
    asm volatile(
        "mma.sync.aligned.m16n8k16.row.col.f32.bf16.bf16.f32 "
        "{%0,%1,%2,%3}, {%4,%5,%6,%7}, {%8,%9}, {%0,%1,%2,%3};"
        : "+f"(c[0]), "+f"(c[1]), "+f"(c[2]), "+f"(c[3])
        : "r"(a[0]), "r"(a[1]), "r"(a[2]), "r"(a[3]), "r"(b0), "r"(b1));
}

// ---------------------------------------------------------------------------
// Prep: hi/lo bf16 split in transposed [b][n][c] layout + fp32 norms.
// ---------------------------------------------------------------------------
__global__ void prep_kernel(const float* __restrict__ x) {
    int b = blockIdx.y;
    int n = blockIdx.x * 128 + threadIdx.x;
    const float* xp = x + b * CC * NN + n;
    __nv_bfloat162 hi2[32], lo2[32];
    float s = 0.f;
#pragma unroll
    for (int c2 = 0; c2 < 32; ++c2) {
        float v0 = xp[(2 * c2) * NN];
        float v1 = xp[(2 * c2 + 1) * NN];
        s = fmaf(v0, v0, s);
        s = fmaf(v1, v1, s);
        __nv_bfloat16 h0 = __float2bfloat16(v0);
        __nv_bfloat16 h1 = __float2bfloat16(v1);
        float r0 = v0 - __bfloat162float(h0);
        float r1 = v1 - __bfloat162float(h1);
        hi2[c2] = __halves2bfloat162(h0, h1);
        lo2[c2] = __halves2bfloat162(__float2bfloat16(r0), __float2bfloat16(r1));
    }
    g_xx[b * NN + n] = s;
    size_t rowo = (size_t)(b * NN + n) * CC;
    uint4* dh = (uint4*)(g_hi + rowo);
    uint4* dl = (uint4*)(g_lo + rowo);
    const uint4* sh = (const uint4*)hi2;
    const uint4* sl = (const uint4*)lo2;
#pragma unroll
    for (int i = 0; i < 8; ++i) { dh[i] = sh[i]; dl[i] = sl[i]; }
}

// ---------------------------------------------------------------------------
// KNN: bf16-split HMMA (mma.sync) + smem score spill + 4-way split scan.
// 256 threads = 8 warps; warp tile 32x32 of the 64x128 score tile.
// ---------------------------------------------------------------------------
__global__ void __launch_bounds__(256, 2) knn_kernel() {
    extern __shared__ char sm[];
    const uint32_t sb = smem_u32(sm);
    const int tid  = threadIdx.x;
    const int lane = tid & 31;
    const int w    = tid >> 5;
    const int wm   = (w & 1) * 32;        // warp's query offset (0/32)
    const int wn   = (w >> 1) * 32;       // warp's candidate offset (0..96)
    const int b    = blockIdx.y;
    const int qbase = blockIdx.x * TQ;

    float* S   = (float*)(sm + SOF);
    float* xxs = (float*)(sm + XXS);

    // Load Q tiles (row = query, 128B bf16 + 16B pad)
    {
        const uint4* qh = (const uint4*)(g_hi + (size_t)(b * NN + qbase) * CC);
        const uint4* ql = (const uint4*)(g_lo + (size_t)(b * NN + qbase) * CC);
        for (int i = tid; i < TQ * 8; i += 256) {
            int row = i >> 3, seg = i & 7;
            int o = row * RS + seg * 16;
            *(uint4*)(sm + QHI + o) = qh[i];
            *(uint4*)(sm + QLO + o) = ql[i];
        }
    }

    float val9[9];
    int   idx9[9];
#pragma unroll
    for (int k = 0; k < 9; ++k) { val9[k] = -3.4e38f; idx9[k] = -1; }

    const int qown = tid & 63;     // query this thread scans
    const int qtr  = tid >> 6;     // candidate quarter (32 wide)

    const int lrow = lane & 15;
    const int lcol = (lane >> 4) * 16;
    const uint32_t aHiBase = sb + QHI + (wm + lrow) * RS + lcol;
    const uint32_t aLoBase = sb + QLO + (wm + lrow) * RS + lcol;
    const uint32_t bHiBase = sb + MHI + (wn + lrow) * RS + lcol;
    const uint32_t bLoBase = sb + MLO + (wn + lrow) * RS + lcol;

    for (int mt = 0; mt < 16; ++mt) {
        const int mb = mt * TM;
        __syncthreads();   // previous scan done (S reusable), M buffers free

        // Load M tiles
        {
            const uint4* mh = (const uint4*)(g_hi + (size_t)(b * NN + mb) * CC);
            const uint4* ml = (const uint4*)(g_lo + (size_t)(b * NN + mb) * CC);
            for (int i = tid; i < TM * 8; i += 256) {
                int row = i >> 3, seg = i & 7;
                int o = row * RS + seg * 16;
                *(uint4*)(sm + MHI + o) = mh[i];
                *(uint4*)(sm + MLO + o) = ml[i];
            }
            if (tid < TM) xxs[tid] = g_xx[b * NN + mb + tid];
        }
        __syncthreads();

        // 64x128 score tile: 3-pass bf16-split accumulated in fp32
        float acc[2][4][4];
#pragma unroll
        for (int i = 0; i < 2; ++i)
#pragma unroll
            for (int j = 0; j < 4; ++j)
#pragma unroll
                for (int k = 0; k < 4; ++k) acc[i][j][k] = 0.f;

#pragma unroll
        for (int ks = 0; ks < 4; ++ks) {
            const int ko = ks * 32;
            uint32_t aH[2][4], aL[2][4], bH[4][2], bL[4][2];
#pragma unroll
            for (int m2 = 0; m2 < 2; ++m2) {
                ldsm4(aH[m2][0], aH[m2][1], aH[m2][2], aH[m2][3], aHiBase + m2 * 16 * RS + ko);
                ldsm4(aL[m2][0], aL[m2][1], aL[m2][2], aL[m2][3], aLoBase + m2 * 16 * RS + ko);
            }
#pragma unroll
            for (int np = 0; np < 2; ++np) {
                uint32_t r0, r1, r2, r3;
                ldsm4(r0, r1, r2, r3, bHiBase + np * 16 * RS + ko);
                bH[np * 2][0] = r0; bH[np * 2][1] = r2;
                bH[np * 2 + 1][0] = r1; bH[np * 2 + 1][1] = r3;
                ldsm4(r0, r1, r2, r3, bLoBase + np * 16 * RS + ko);
                bL[np * 2][0] = r0; bL[np * 2][1] = r2;
                bL[np * 2 + 1][0] = r1; bL[np * 2 + 1][1] = r3;
            }
#pragma unroll
            for (int m2 = 0; m2 < 2; ++m2)
#pragma unroll
                for (int j = 0; j < 4; ++j) {
                    mma16816(acc[m2][j], aH[m2], bH[j][0], bH[j][1]);
                    mma16816(acc[m2][j], aH[m2], bL[j][0], bL[j][1]);
                    mma16816(acc[m2][j], aL[m2], bH[j][0], bH[j][1]);
                }
        }

        // Spill scores to S (row = query, col = candidate)
        {
            const int r  = lane >> 2;
            const int cp = (lane & 3) * 2;
#pragma unroll
            for (int m2 = 0; m2 < 2; ++m2)
#pragma unroll
                for (int j = 0; j < 4; ++j) {
                    int row = wm + m2 * 16 + r;
                    int col = wn + j * 8 + cp;
                    S[row * SROW + col]           = acc[m2][j][0];
                    S[row * SROW + col + 1]       = acc[m2][j][1];
                    S[(row + 8) * SROW + col]     = acc[m2][j][2];
                    S[(row + 8) * SROW + col + 1] = acc[m2][j][3];
                }
        }
        __syncthreads();

        // Scan: 4 threads per query, 32 candidates each, persistent top-9
        {
            const float* srow = &S[qown * SROW + qtr * 32];
            const float* xxp  = &xxs[qtr * 32];
            const int mofs = mb + qtr * 32;
#pragma unroll 4
            for (int m = 0; m < 32; ++m) {
                float v = fmaf(2.f, srow[m], -xxp[m]);
                if (v > val9[8]) {
                    val9[8] = v;
                    idx9[8] = mofs + m;
#pragma unroll
                    for (int k = 8; k > 0; --k) {
                        if (val9[k] > val9[k - 1]) {
                            float tv = val9[k]; val9[k] = val9[k - 1]; val9[k - 1] = tv;
                            int   ti = idx9[k]; idx9[k] = idx9[k - 1]; idx9[k - 1] = ti;
                        }
                    }
                }
            }
        }
    }

    // Stable 4-way merge per query (val desc, idx asc — matches top_k)
    __syncthreads();
    float* MV = (float*)(sm + SOF);                       // [4*64][9]
    int*   MI = (int*)(sm + SOF + 4 * 64 * 9 * 4);        // [4*64][9]
#pragma unroll
    for (int k = 0; k < 9; ++k) {
        MV[(qtr * 64 + qown) * 9 + k] = val9[k];
        MI[(qtr * 64 + qown) * 9 + k] = idx9[k];
    }
    __syncthreads();
    if (tid < TQ) {
        int p[4] = {0, 0, 0, 0};
        int* gout = &g_idx[(size_t)(b * NN + qbase + tid) * 8];
#pragma unroll
        for (int k = 0; k < 9; ++k) {
            float bv = -3.4e38f;
            int   bi = 0x7FFFFFFF, bl = 0;
#pragma unroll
            for (int l = 0; l < 4; ++l) {
                if (p[l] < 9) {
                    float v = MV[(l * 64 + tid) * 9 + p[l]];
                    int   i = MI[(l * 64 + tid) * 9 + p[l]];
                    if (v > bv || (v == bv && i < bi)) { bv = v; bi = i; bl = l; }
                }
            }
            ++p[bl];
            if (k > 0) gout[k - 1] = bi;
        }
    }
}

// ---------------------------------------------------------------------------
// Output assembly:
// out[b,c,n] = x[b,c,n];  out[b,c,N+n] = mean_k x[b,c,idx[b,n,k]]
// ---------------------------------------------------------------------------
__global__ void gather_kernel(const float* __restrict__ x, float* __restrict__ out) {
    __shared__ float row[NN];
    int b = blockIdx.x >> 6;
    int c = blockIdx.x & 63;
    const float* xr = x + (b * CC + c) * NN;
    for (int n = threadIdx.x; n < NN; n += blockDim.x) row[n] = xr[n];
    __syncthreads();
    const int* gi = g_idx + b * NN * 8;
    float* o = out + (size_t)(b * CC + c) * (2 * NN);
    for (int n = threadIdx.x; n < NN; n += blockDim.x) {
        o[n] = row[n];
        const int* gn = gi + n * 8;
        float s = 0.f;
#pragma unroll
        for (int k = 0; k < 8; ++k) s += row[gn[k]];
        o[NN + n] = s * 0.125f;
    }
}

// ---------------------------------------------------------------------------
extern "C" void kernel_launch(void* const* d_in, const int* in_sizes, int n_in,
                              void* d_out, int out_size) {
    (void)in_sizes; (void)n_in; (void)out_size;
    const float* x = (const float*)d_in[0];
    float* out = (float*)d_out;

    prep_kernel<<<dim3(NN / 128, BB), 128>>>(x);

    cudaFuncSetAttribute(knn_kernel, cudaFuncAttributeMaxDynamicSharedMemorySize, SM_TOTAL);
    knn_kernel<<<dim3(NN / TQ, BB), 256, SM_TOTAL>>>();

    gather_kernel<<<BB * CC, 256>>>(x, out);
}

// round 5
// speedup vs baseline: 1.5183x; 1.0898x over previous
#include <cuda_runtime.h>
#include <cuda_bf16.h>
#include <cstdint>

#define BB 16
#define CC 64
#define NN 2048
#define RS 144     // bf16 tile row stride (bytes): 128 data + 16 pad
#define SROW 129   // fp32 score row stride (words)
#define NTILE 136  // 16*17/2 upper-triangle tiles

// ---------------- scratch (no allocation allowed) ----------------
__device__ __nv_bfloat16 g_hi[BB * NN * CC];   // [b][n][c]
__device__ __nv_bfloat16 g_lo[BB * NN * CC];
__device__ float         g_xx[BB * NN];
__device__ float         g_pv[(size_t)BB * NN * 16 * 9];   // partial top-9 vals
__device__ int           g_pi[(size_t)BB * NN * 16 * 9];   // partial top-9 idx
__device__ int           g_idx[BB * NN * 8];

// smem layout (bytes)
#define AHI 0
#define ALO (AHI + 128 * RS)       // 18432
#define BHI (ALO + 128 * RS)       // 36864
#define BLO (BHI + 128 * RS)       // 55296
#define XXA (BLO + 128 * RS)       // 73728
#define XXB (XXA + 512)            // 74240
#define SM_TOTAL (XXB + 512)       // 74752;  S[128][129] fp32 aliases bytes [0, 66048)

__device__ __forceinline__ uint32_t smem_u32(const void* p) {
    uint32_t a;
    asm("{ .reg .u64 t; cvta.to.shared.u64 t, %1; cvt.u32.u64 %0, t; }" : "=r"(a) : "l"(p));
    return a;
}
__device__ __forceinline__ void ldsm4(uint32_t& r0, uint32_t& r1, uint32_t& r2, uint32_t& r3,
                                      uint32_t addr) {
    asm volatile("ldmatrix.sync.aligned.m8n8.x4.shared.b16 {%0,%1,%2,%3}, [%4];"
                 : "=r"(r0), "=r"(r1), "=r"(r2), "=r"(r3) : "r"(addr));
}
__device__ __forceinline__ void mma16816(float* c, const uint32_t* a, uint32_t b0, uint32_t b1) {
    asm volatile(
        "mma.sync.aligned.m16n8k16.row.col.f32.bf16.bf16.f32 "
        "{%0,%1,%2,%3}, {%4,%5,%6,%7}, {%8,%9}, {%0,%1,%2,%3};"
        : "+f"(c[0]), "+f"(c[1]), "+f"(c[2]), "+f"(c[3])
        : "r"(a[0]), "r"(a[1]), "r"(a[2]), "r"(a[3]), "r"(b0), "r"(b1));
}

// ---------------------------------------------------------------------------
// Prep: hi/lo bf16 split in transposed [b][n][c] layout + fp32 norms.
// ---------------------------------------------------------------------------
__global__ void prep_kernel(const float* __restrict__ x) {
    int b = blockIdx.y;
    int n = blockIdx.x * 128 + threadIdx.x;
    const float* xp = x + b * CC * NN + n;
    __nv_bfloat162 hi2[32], lo2[32];
    float s = 0.f;
#pragma unroll
    for (int c2 = 0; c2 < 32; ++c2) {
        float v0 = xp[(2 * c2) * NN];
        float v1 = xp[(2 * c2 + 1) * NN];
        s = fmaf(v0, v0, s);
        s = fmaf(v1, v1, s);
        __nv_bfloat16 h0 = __float2bfloat16(v0);
        __nv_bfloat16 h1 = __float2bfloat16(v1);
        float r0 = v0 - __bfloat162float(h0);
        float r1 = v1 - __bfloat162float(h1);
        hi2[c2] = __halves2bfloat162(h0, h1);
        lo2[c2] = __halves2bfloat162(__float2bfloat16(r0), __float2bfloat16(r1));
    }
    g_xx[b * NN + n] = s;
    size_t rowo = (size_t)(b * NN + n) * CC;
    uint4* dh = (uint4*)(g_hi + rowo);
    uint4* dl = (uint4*)(g_lo + rowo);
    const uint4* sh = (const uint4*)hi2;
    const uint4* sl = (const uint4*)lo2;
#pragma unroll
    for (int i = 0; i < 8; ++i) { dh[i] = sh[i]; dl[i] = sl[i]; }
}

// ---------------------------------------------------------------------------
// top-9 insert: strict >, candidates arrive in ascending index order,
// stable bubble => exact top_k (val desc, idx asc) semantics.
// ---------------------------------------------------------------------------
#define INS9(v, ii)                                                          \
    if ((v) > val9[8]) {                                                     \
        val9[8] = (v); idx9[8] = (ii);                                       \
        _Pragma("unroll")                                                    \
        for (int k = 8; k > 0; --k) {                                        \
            if (val9[k] > val9[k - 1]) {                                     \
                float tv = val9[k]; val9[k] = val9[k - 1]; val9[k - 1] = tv; \
                int   ti_ = idx9[k]; idx9[k] = idx9[k - 1]; idx9[k - 1] = ti_; \
            }                                                                \
        }                                                                    \
    }

// ---------------------------------------------------------------------------
// KNN tile kernel: one CTA = one upper-triangle 128x128 tile (ti <= tj).
// 256 threads / 8 warps, warp tile 32x64, bf16-split 3-pass HMMA.
// Then row scan (queries block ti) + col scan (queries block tj) in parallel.
// ---------------------------------------------------------------------------
__global__ void __launch_bounds__(256, 2) knn_kernel() {
    extern __shared__ char sm[];
    const uint32_t sb = smem_u32(sm);
    const int tid  = threadIdx.x;
    const int lane = tid & 31;
    const int w    = tid >> 5;
    const int wrow = (w >> 1) * 32;       // warp query-row offset (0..96)
    const int wcol = (w & 1) * 64;        // warp candidate-col offset (0/64)
    const int b    = blockIdx.y;

    // decode upper-triangle tile (ti, tj)
    int t = blockIdx.x, ti = 0;
    while (t >= 16 - ti) { t -= 16 - ti; ++ti; }
    const int tj = ti + t;

    float* S   = (float*)sm;              // aliases A/B tiles after MMA
    float* xxA = (float*)(sm + XXA);
    float* xxB = (float*)(sm + XXB);

    // ---- load tiles ----
    {
        const uint4* ah = (const uint4*)(g_hi + (size_t)(b * NN + ti * 128) * CC);
        const uint4* al = (const uint4*)(g_lo + (size_t)(b * NN + ti * 128) * CC);
        const uint4* bh = (const uint4*)(g_hi + (size_t)(b * NN + tj * 128) * CC);
        const uint4* bl = (const uint4*)(g_lo + (size_t)(b * NN + tj * 128) * CC);
        for (int i = tid; i < 1024; i += 256) {
            int row = i >> 3, seg = i & 7;
            int o = row * RS + seg * 16;
            *(uint4*)(sm + AHI + o) = ah[i];
            *(uint4*)(sm + ALO + o) = al[i];
            *(uint4*)(sm + BHI + o) = bh[i];
            *(uint4*)(sm + BLO + o) = bl[i];
        }
        if (tid < 128)      xxA[tid] = g_xx[b * NN + ti * 128 + tid];
        else                xxB[tid - 128] = g_xx[b * NN + tj * 128 + (tid - 128)];
    }
    __syncthreads();

    // ---- MMA: 128x128 tile, 3-pass split ----
    float acc[2][8][4];
#pragma unroll
    for (int i = 0; i < 2; ++i)
#pragma unroll
        for (int j = 0; j < 8; ++j)
#pragma unroll
            for (int k = 0; k < 4; ++k) acc[i][j][k] = 0.f;

    const int lrow = lane & 15;
    const int lcol = (lane >> 4) * 16;
    const uint32_t aHiB = sb + AHI + (wrow + lrow) * RS + lcol;
    const uint32_t aLoB = sb + ALO + (wrow + lrow) * RS + lcol;
    const uint32_t bHiB = sb + BHI + (wcol + lrow) * RS + lcol;
    const uint32_t bLoB = sb + BLO + (wcol + lrow) * RS + lcol;

#pragma unroll
    for (int ks = 0; ks < 4; ++ks) {
        const int ko = ks * 32;    // bytes: 16 bf16 per k-step
        uint32_t aH[2][4], aL[2][4];
#pragma unroll
        for (int m2 = 0; m2 < 2; ++m2) {
            ldsm4(aH[m2][0], aH[m2][1], aH[m2][2], aH[m2][3], aHiB + m2 * 16 * RS + ko);
            ldsm4(aL[m2][0], aL[m2][1], aL[m2][2], aL[m2][3], aLoB + m2 * 16 * RS + ko);
        }
#pragma unroll
        for (int ng = 0; ng < 4; ++ng) {
            uint32_t h0, h1, h2, h3, l0, l1, l2, l3;
            ldsm4(h0, h1, h2, h3, bHiB + ng * 16 * RS + ko);
            ldsm4(l0, l1, l2, l3, bLoB + ng * 16 * RS + ko);
#pragma unroll
            for (int m2 = 0; m2 < 2; ++m2) {
                mma16816(acc[m2][ng * 2],     aH[m2], h0, h2);
                mma16816(acc[m2][ng * 2 + 1], aH[m2], h1, h3);
                mma16816(acc[m2][ng * 2],     aH[m2], l0, l2);
                mma16816(acc[m2][ng * 2 + 1], aH[m2], l1, l3);
                mma16816(acc[m2][ng * 2],     aL[m2], h0, h2);
                mma16816(acc[m2][ng * 2 + 1], aL[m2], h1, h3);
            }
        }
    }
    __syncthreads();   // tiles no longer needed; S may overwrite

    // ---- spill S[q][m] ----
    {
        const int r  = lane >> 2;
        const int cp = (lane & 3) * 2;
#pragma unroll
        for (int m2 = 0; m2 < 2; ++m2)
#pragma unroll
            for (int j = 0; j < 8; ++j) {
                int row = wrow + m2 * 16 + r;
                int col = wcol + j * 8 + cp;
                S[row * SROW + col]           = acc[m2][j][0];
                S[row * SROW + col + 1]       = acc[m2][j][1];
                S[(row + 8) * SROW + col]     = acc[m2][j][2];
                S[(row + 8) * SROW + col + 1] = acc[m2][j][3];
            }
    }
    __syncthreads();

    // ---- scans ----
    float val9[9];
    int   idx9[9];
#pragma unroll
    for (int k = 0; k < 9; ++k) { val9[k] = -3.4e38f; idx9[k] = 0x7FFFFFFF; }

    if (tid < 128) {
        // row scan: query = ti*128 + tid, candidates = block tj
        const float* srow = &S[tid * SROW];
        const int base = tj * 128;
        for (int m = 0; m < 128; ++m) {
            float v = fmaf(2.f, srow[m], -xxB[m]);
            INS9(v, base + m);
        }
        size_t o = ((size_t)(b * NN + ti * 128 + tid) * 16 + tj) * 9;
#pragma unroll
        for (int k = 0; k < 9; ++k) { g_pv[o + k] = val9[k]; g_pi[o + k] = idx9[k]; }
    } else if (ti != tj) {
        // col scan: query = tj*128 + (tid-128), candidates = block ti
        const int q = tid - 128;
        const int base = ti * 128;
        for (int m = 0; m < 128; ++m) {
            float v = fmaf(2.f, S[m * SROW + q], -xxA[m]);
            INS9(v, base + m);
        }
        size_t o = ((size_t)(b * NN + tj * 128 + q) * 16 + ti) * 9;
#pragma unroll
        for (int k = 0; k < 9; ++k) { g_pv[o + k] = val9[k]; g_pi[o + k] = idx9[k]; }
    }
}

// ---------------------------------------------------------------------------
// Merge: per query, merge 16 sorted partial top-9 lists (slot order =
// ascending candidate block => stable). Output ranks 1..8 (rank 0 = self).
// ---------------------------------------------------------------------------
__global__ void merge_kernel() {
    int q = blockIdx.x * 256 + threadIdx.x;      // 0 .. BB*NN-1
    const float* pv = g_pv + (size_t)q * 144;
    const int*   pi = g_pi + (size_t)q * 144;
    float val9[9];
    int   idx9[9];
#pragma unroll
    for (int k = 0; k < 9; ++k) { val9[k] = -3.4e38f; idx9[k] = 0x7FFFFFFF; }
    for (int s = 0; s < 16; ++s) {
#pragma unroll
        for (int k = 0; k < 9; ++k) {
            float v = pv[s * 9 + k];
            if (v <= val9[8]) break;             // list is sorted desc
            int ii = pi[s * 9 + k];
            INS9(v, ii);
        }
    }
    int* gout = &g_idx[(size_t)q * 8];
#pragma unroll
    for (int k = 0; k < 8; ++k) gout[k] = idx9[k + 1];
}

// ---------------------------------------------------------------------------
// Output assembly:
// out[b,c,n] = x[b,c,n];  out[b,c,N+n] = mean_k x[b,c,idx[b,n,k]]
// ---------------------------------------------------------------------------
__global__ void gather_kernel(const float* __restrict__ x, float* __restrict__ out) {
    __shared__ float row[NN];
    int b = blockIdx.x >> 6;
    int c = blockIdx.x & 63;
    const float* xr = x + (b * CC + c) * NN;
    for (int n = threadIdx.x; n < NN; n += blockDim.x) row[n] = xr[n];
    __syncthreads();
    const int4* gi = (const int4*)(g_idx + (size_t)b * NN * 8);
    float* o = out + (size_t)(b * CC + c) * (2 * NN);
    for (int n = threadIdx.x; n < NN; n += blockDim.x) {
        o[n] = row[n];
        int4 i0 = gi[n * 2];
        int4 i1 = gi[n * 2 + 1];
        float s = row[i0.x] + row[i0.y] + row[i0.z] + row[i0.w]
                + row[i1.x] + row[i1.y] + row[i1.z] + row[i1.w];
        o[NN + n] = s * 0.125f;
    }
}

// ---------------------------------------------------------------------------
extern "C" void kernel_launch(void* const* d_in, const int* in_sizes, int n_in,
                              void* d_out, int out_size) {
    (void)in_sizes; (void)n_in; (void)out_size;
    const float* x = (const float*)d_in[0];
    float* out = (float*)d_out;

    prep_kernel<<<dim3(NN / 128, BB), 128>>>(x);

    cudaFuncSetAttribute(knn_kernel, cudaFuncAttributeMaxDynamicSharedMemorySize, SM_TOTAL);
    knn_kernel<<<dim3(NTILE, BB), 256, SM_TOTAL>>>();

    merge_kernel<<<(BB * NN) / 256, 256>>>();

    gather_kernel<<<BB * CC, 256>>>(x, out);
}